// round 14
// baseline (speedup 1.0000x reference)
#include <cuda_runtime.h>
#include <cuda_bf16.h>
#include <math.h>

// ---------------- problem constants ----------------
#define TOK    6272
#define LSEQ   3136
#define HH     56
#define WWW    56
#define DM     96
#define DI     192
#define N2     384
#define NST    16
#define RK     6
#define GSEQ   8
#define NCH    56
#define CLEN   56
#define SEG    (DI * NST)   // 3072 states per (g,chunk)

// ---------------- scratch ----------------
__device__ float  g_xm [TOK * DI];
__device__ float  g_z  [TOK * DI];
__device__ __align__(16) float2 g_dtx[TOK * DI];           // (dt, x_conv)
__device__ float  g_Bv [TOK * NST];
__device__ float  g_Cv [TOK * NST];
__device__ __align__(16) float2 g_ab [GSEQ * NCH * SEG];   // (a_prod, h_end)
__device__ __align__(16) float  g_hs [GSEQ * NCH * SEG];   // h_start
__device__ float  g_ys [GSEQ * LSEQ * DI];

typedef unsigned long long u64;
__device__ __forceinline__ float ex2(float x) {
    float r; asm("ex2.approx.f32 %0, %1;" : "=f"(r) : "f"(x)); return r;
}
__device__ __forceinline__ u64 pack2(float lo, float hi) {
    u64 r; asm("mov.b64 %0, {%1, %2};" : "=l"(r) : "f"(lo), "f"(hi)); return r;
}
__device__ __forceinline__ void unpack2(u64 v, float& lo, float& hi) {
    asm("mov.b64 {%0, %1}, %2;" : "=f"(lo), "=f"(hi) : "l"(v));
}
__device__ __forceinline__ u64 fma2(u64 a, u64 b, u64 c) {
    u64 d; asm("fma.rn.f32x2 %0, %1, %2, %3;" : "=l"(d) : "l"(a), "l"(b), "l"(c)); return d;
}
__device__ __forceinline__ u64 mul2(u64 a, u64 b) {
    u64 d; asm("mul.rn.f32x2 %0, %1, %2;" : "=l"(d) : "l"(a), "l"(b)); return d;
}

__device__ __forceinline__ void seq_base(int d, int b, int ch, int& t0, int& st) {
    if      (d == 0) { t0 = b * LSEQ + ch * WWW;      st = 1;   }
    else if (d == 1) { t0 = b * LSEQ + ch * WWW + 55; st = -1;  }
    else if (d == 2) { t0 = b * LSEQ + ch;            st = WWW; }
    else             { t0 = b * LSEQ + (55 - ch);     st = WWW; }
}

// ---------------- kernel 1: xz = x @ W_in -> xm / z ----------------
__global__ void __launch_bounds__(256) k_inproj(const float* __restrict__ x,
                                                const float* __restrict__ Wi) {
    __shared__ float sx[48 * 64];
    __shared__ float sw[48 * 128];
    const int m0 = blockIdx.x * 64;
    const int n0 = blockIdx.y * 128;
    const int tid = threadIdx.x;
    const int tm = tid >> 4;
    const int tn = tid & 15;
    float acc[4][8] = {};
    for (int k0 = 0; k0 < 96; k0 += 48) {
        __syncthreads();
        for (int idx = tid; idx < 64 * 48; idx += 256) {
            int i = idx / 48, kk = idx - i * 48;
            sx[kk * 64 + i] = x[(m0 + i) * 96 + k0 + kk];
        }
        for (int idx = tid; idx < 48 * 128; idx += 256) {
            int kk = idx >> 7, nn = idx & 127;
            sw[kk * 128 + nn] = Wi[(k0 + kk) * 384 + n0 + nn];
        }
        __syncthreads();
#pragma unroll
        for (int kk = 0; kk < 48; kk++) {
            float4 a  = *(const float4*)&sx[kk * 64  + tm * 4];
            float4 b0 = *(const float4*)&sw[kk * 128 + tn * 8];
            float4 b1 = *(const float4*)&sw[kk * 128 + tn * 8 + 4];
            float av[4] = {a.x, a.y, a.z, a.w};
            float bv[8] = {b0.x, b0.y, b0.z, b0.w, b1.x, b1.y, b1.z, b1.w};
#pragma unroll
            for (int i = 0; i < 4; i++)
#pragma unroll
                for (int j = 0; j < 8; j++)
                    acc[i][j] = fmaf(av[i], bv[j], acc[i][j]);
        }
    }
#pragma unroll
    for (int i = 0; i < 4; i++) {
        int m = m0 + tm * 4 + i;
#pragma unroll
        for (int j = 0; j < 8; j++) {
            int n = n0 + tn * 8 + j;
            if (n < DI) g_xm[m * DI + n] = acc[i][j];
            else        g_z [m * DI + (n - DI)] = acc[i][j];
        }
    }
}

// ---------------- kernel 2: fused conv3x3 + x-proj + dt-proj ----------------
#define SXP 193
#define XN  40
__global__ void __launch_bounds__(256) k_fuse(const float* __restrict__ cw,
                                              const float* __restrict__ cb,
                                              const float* __restrict__ Wx,
                                              const float* __restrict__ Wd,
                                              const float* __restrict__ bd) {
    __shared__ float sxc[32 * SXP];
    __shared__ float sw[48 * XN];
    __shared__ float swd[RK * DI];
    __shared__ float sbd[DI];
    __shared__ float sdtr[32 * 8];
    __shared__ float scw[9 * DI];
    __shared__ float scb[DI];
    const int t0 = blockIdx.x * 32;
    const int tid = threadIdx.x;

    for (int idx = tid; idx < RK * DI; idx += 256) swd[idx] = Wd[idx];
    for (int idx = tid; idx < 9 * DI; idx += 256) scw[idx] = cw[idx];
    if (tid < DI) { sbd[tid] = bd[tid]; scb[tid] = cb[tid]; }
    __syncthreads();

    // conv phase
    for (int idx = tid; idx < 32 * DI; idx += 256) {
        int i = idx / DI, c = idx - i * DI;
        int t = t0 + i;
        int b = t / LSEQ, r = t - b * LSEQ, h = r / WWW, w = r - h * WWW;
        float acc = scb[c];
#pragma unroll
        for (int dh = -1; dh <= 1; dh++)
#pragma unroll
            for (int dw = -1; dw <= 1; dw++) {
                int hh = h + dh, ww = w + dw;
                if ((unsigned)hh < HH && (unsigned)ww < WWW)
                    acc = fmaf(g_xm[(b * LSEQ + hh * WWW + ww) * DI + c],
                               scw[((dh + 1) * 3 + (dw + 1)) * DI + c], acc);
            }
        sxc[i * SXP + c] = acc;
    }

    // x-proj GEMM: M=32, N=38(pad 40), K=192
    const int tm = tid >> 3;
    const int tn = tid & 7;
    float acc[5] = {};
    for (int k0 = 0; k0 < 192; k0 += 48) {
        __syncthreads();
        for (int idx = tid; idx < 48 * XN; idx += 256) {
            int kk = idx / XN, nn = idx - kk * XN;
            sw[idx] = (nn < 38) ? Wx[(k0 + kk) * 38 + nn] : 0.f;
        }
        __syncthreads();
#pragma unroll
        for (int kk = 0; kk < 48; kk++) {
            float a = sxc[tm * SXP + k0 + kk];
            const float* wr = &sw[kk * XN + tn * 5];
#pragma unroll
            for (int j = 0; j < 5; j++) acc[j] = fmaf(a, wr[j], acc[j]);
        }
    }
#pragma unroll
    for (int j = 0; j < 5; j++) {
        int n = tn * 5 + j;
        if (n < RK)            sdtr[tm * 8 + n] = acc[j];
        else if (n < RK + NST) g_Bv[(t0 + tm) * NST + n - RK] = acc[j];
        else if (n < 38)       g_Cv[(t0 + tm) * NST + n - RK - NST] = acc[j];
    }
    __syncthreads();

    // dt-proj + softplus, pack with conv output
#pragma unroll
    for (int p = 0; p < 24; p++) {
        int idx = p * 256 + tid;
        int i = idx / DI, c = idx - i * DI;
        float a = sbd[c];
#pragma unroll
        for (int r = 0; r < RK; r++) a = fmaf(sdtr[i * 8 + r], swd[r * DI + c], a);
        float dt = (a > 20.f) ? a : log1pf(expf(a));
        g_dtx[(t0 + i) * DI + c] = make_float2(dt, sxc[i * SXP + c]);
    }
}

// ---------------- kernel 3: scan pass 1 ----------------
__global__ void __launch_bounds__(192) k_scan1(const float* __restrict__ A_log) {
    const int bx = blockIdx.x;
    const int ch = bx % NCH, g = bx / NCH;
    const int d = g >> 1, b = g & 1;
    __shared__ __align__(16) float s_B[CLEN * NST];
    int t0, st; seq_base(d, b, ch, t0, st);
    const int c = threadIdx.x;
    for (int idx = c; idx < CLEN * NST; idx += 192) {
        int l = idx >> 4, n = idx & 15;
        s_B[idx] = g_Bv[(t0 + l * st) * NST + n];
    }
    float acl[16];
#pragma unroll
    for (int q = 0; q < 4; q++) {
        float4 v = ((const float4*)A_log)[c * 4 + q];
        acl[q*4+0] = -__expf(v.x) * 1.4426950408889634f;
        acl[q*4+1] = -__expf(v.y) * 1.4426950408889634f;
        acl[q*4+2] = -__expf(v.z) * 1.4426950408889634f;
        acl[q*4+3] = -__expf(v.w) * 1.4426950408889634f;
    }
    u64 acl2[8], h2[8];
#pragma unroll
    for (int q = 0; q < 8; q++) { acl2[q] = pack2(acl[2*q], acl[2*q+1]); h2[q] = 0ull; }
    __syncthreads();
    const int stride = st * DI;
    const float2* pdx = g_dtx + t0 * DI + c;
    float2 cur = *pdx;
    float S = 0.f;
#pragma unroll 2
    for (int l = 0; l < CLEN; l++) {
        float dt = cur.x, xv = cur.y;
        if (l < CLEN - 1) { pdx += stride; cur = *pdx; }
        S += dt;
        float dtx = dt * xv;
        u64 dt2  = pack2(dt, dt);
        u64 dtx2 = pack2(dtx, dtx);
        const u64* b2 = (const u64*)(s_B + l * 16);
#pragma unroll
        for (int q = 0; q < 8; q++) {
            u64 arg = mul2(dt2, acl2[q]);
            float alo, ahi; unpack2(arg, alo, ahi);
            u64 a2 = pack2(ex2(alo), ex2(ahi));
            h2[q] = fma2(a2, h2[q], mul2(dtx2, b2[q]));
        }
    }
    float4* pw = (float4*)&g_ab[(bx * DI + c) * NST];
#pragma unroll
    for (int q = 0; q < 8; q++) {
        float h0, h1; unpack2(h2[q], h0, h1);
        pw[q] = make_float4(ex2(acl[2*q] * S), h0, ex2(acl[2*q+1] * S), h1);
    }
}

// ---------------- kernel 4: cross-chunk prefix combine ----------------
__global__ void __launch_bounds__(128) k_combine() {
    const int s = blockIdx.x * 128 + threadIdx.x;   // 24576
    const int g = s / SEG, sc = s - g * SEG;
    const float2* pab = g_ab + g * NCH * SEG + sc;
    float* phs = g_hs + g * NCH * SEG + sc;
    float h = 0.f;
#pragma unroll
    for (int half = 0; half < 2; half++) {
        float2 v[28];
#pragma unroll
        for (int j = 0; j < 28; j++) v[j] = pab[(half * 28 + j) * SEG];
#pragma unroll
        for (int j = 0; j < 28; j++) {
            phs[(half * 28 + j) * SEG] = h;
            h = fmaf(v[j].x, h, v[j].y);
        }
    }
}

// ---------------- kernel 5: scan pass 2 (replay + emit y) ----------------
__global__ void __launch_bounds__(192) k_scan2(const float* __restrict__ A_log,
                                               const float* __restrict__ D_skip) {
    const int bx = blockIdx.x;
    const int ch = bx % NCH, g = bx / NCH;
    const int d = g >> 1, b = g & 1;
    __shared__ __align__(16) float s_B[CLEN * NST];
    __shared__ __align__(16) float s_C[CLEN * NST];
    int t0, st; seq_base(d, b, ch, t0, st);
    const int c = threadIdx.x;
    for (int idx = c; idx < CLEN * NST * 2; idx += 192) {
        int half = idx >= CLEN * NST;
        int r = idx - half * CLEN * NST;
        int l = r >> 4, n = r & 15;
        int t = t0 + l * st;
        if (half) s_C[r] = g_Cv[t * NST + n];
        else      s_B[r] = g_Bv[t * NST + n];
    }
    float acl[16];
#pragma unroll
    for (int q = 0; q < 4; q++) {
        float4 v = ((const float4*)A_log)[c * 4 + q];
        acl[q*4+0] = -__expf(v.x) * 1.4426950408889634f;
        acl[q*4+1] = -__expf(v.y) * 1.4426950408889634f;
        acl[q*4+2] = -__expf(v.z) * 1.4426950408889634f;
        acl[q*4+3] = -__expf(v.w) * 1.4426950408889634f;
    }
    u64 acl2[8], h2[8];
    const int base = (bx * DI + c) * NST;
    const u64* phs = (const u64*)&g_hs[base];
#pragma unroll
    for (int q = 0; q < 8; q++) { acl2[q] = pack2(acl[2*q], acl[2*q+1]); h2[q] = phs[q]; }
    const float dsk = D_skip[c];
    __syncthreads();
    const int stride = st * DI;
    const float2* pdx = g_dtx + t0 * DI + c;
    float2 cur = *pdx;
    float* py = g_ys + (g * LSEQ + ch * CLEN) * DI + c;
#pragma unroll 2
    for (int l = 0; l < CLEN; l++) {
        float dt = cur.x, xv = cur.y;
        if (l < CLEN - 1) { pdx += stride; cur = *pdx; }
        float dtx = dt * xv;
        u64 dt2  = pack2(dt, dt);
        u64 dtx2 = pack2(dtx, dtx);
        const u64* b2 = (const u64*)(s_B + l * 16);
        const u64* c2 = (const u64*)(s_C + l * 16);
        u64 y2 = 0ull;
#pragma unroll
        for (int q = 0; q < 8; q++) {
            u64 arg = mul2(dt2, acl2[q]);
            float alo, ahi; unpack2(arg, alo, ahi);
            u64 a2 = pack2(ex2(alo), ex2(ahi));
            h2[q] = fma2(a2, h2[q], mul2(dtx2, b2[q]));
            y2 = fma2(h2[q], c2[q], y2);
        }
        float ylo, yhi; unpack2(y2, ylo, yhi);
        py[l * DI] = fmaf(dsk, xv, ylo + yhi);
    }
}

// ---------------- kernel 6: sum dirs, silu gate, out-proj ----------------
__global__ void __launch_bounds__(256) k_final(const float* __restrict__ Wo,
                                               float* __restrict__ out) {
    __shared__ float syT[192 * 36];
    __shared__ float sw[48 * 96];
    const int t0 = blockIdx.x * 32;
    const int tid = threadIdx.x;
    for (int idx = tid; idx < 32 * 192; idx += 256) {
        int i = idx / 192, c = idx - i * 192;
        int t = t0 + i; int b = t / LSEQ; int l = t - b * LSEQ;
        float ys = 0.f;
#pragma unroll
        for (int dd = 0; dd < 4; dd++)
            ys += g_ys[((dd * 2 + b) * LSEQ + l) * DI + c];
        float z = g_z[t * DI + c];
        syT[c * 36 + i] = ys * (z / (1.f + __expf(-z)));
    }
    const int tm = tid >> 5;
    const int tn = tid & 31;
    float acc[4][3] = {};
    for (int k0 = 0; k0 < 192; k0 += 48) {
        __syncthreads();
        for (int idx = tid; idx < 48 * 96; idx += 256) {
            int kk = idx / 96, nn = idx - kk * 96;
            sw[idx] = Wo[(k0 + kk) * 96 + nn];
        }
        __syncthreads();
#pragma unroll
        for (int kk = 0; kk < 48; kk++) {
            float4 a = *(const float4*)&syT[(k0 + kk) * 36 + tm * 4];
            float w0 = sw[kk * 96 + tn];
            float w1 = sw[kk * 96 + 32 + tn];
            float w2 = sw[kk * 96 + 64 + tn];
            float av[4] = {a.x, a.y, a.z, a.w};
#pragma unroll
            for (int i = 0; i < 4; i++) {
                acc[i][0] = fmaf(av[i], w0, acc[i][0]);
                acc[i][1] = fmaf(av[i], w1, acc[i][1]);
                acc[i][2] = fmaf(av[i], w2, acc[i][2]);
            }
        }
    }
#pragma unroll
    for (int i = 0; i < 4; i++) {
        int t = t0 + tm * 4 + i;
        out[t * DM + tn]      = acc[i][0];
        out[t * DM + 32 + tn] = acc[i][1];
        out[t * DM + 64 + tn] = acc[i][2];
    }
}

// ---------------- launcher ----------------
extern "C" void kernel_launch(void* const* d_in, const int* in_sizes, int n_in,
                              void* d_out, int out_size) {
    const float* x      = (const float*)d_in[0];
    const float* W_in   = (const float*)d_in[1];
    const float* conv_w = (const float*)d_in[2];
    const float* conv_b = (const float*)d_in[3];
    const float* W_xpr  = (const float*)d_in[4];
    const float* W_dt   = (const float*)d_in[5];
    const float* b_dt   = (const float*)d_in[6];
    const float* A_log  = (const float*)d_in[7];
    const float* D_skip = (const float*)d_in[8];
    const float* W_out  = (const float*)d_in[9];
    float* out = (float*)d_out;

    dim3 g1(TOK / 64, N2 / 128);
    k_inproj<<<g1, 256>>>(x, W_in);
    k_fuse<<<TOK / 32, 256>>>(conv_w, conv_b, W_xpr, W_dt, b_dt);
    k_scan1<<<GSEQ * NCH, 192>>>(A_log);
    k_combine<<<GSEQ * SEG / 128, 128>>>();
    k_scan2<<<GSEQ * NCH, 192>>>(A_log, D_skip);
    k_final<<<TOK / 32, 256>>>(W_out, out);
}

// round 15
// speedup vs baseline: 1.0002x; 1.0002x over previous
#include <cuda_runtime.h>
#include <cuda_bf16.h>
#include <math.h>

// ---------------- problem constants ----------------
#define TOK    6272
#define LSEQ   3136
#define HH     56
#define WWW    56
#define DM     96
#define DI     192
#define N2     384
#define NST    16
#define RK     6
#define GSEQ   8
#define NCH    56
#define CLEN   56
#define SEG    (DI * NST)   // 3072 states per (g,chunk)

// ---------------- scratch ----------------
__device__ float  g_xm [TOK * DI];
__device__ float  g_z  [TOK * DI];
__device__ __align__(16) float2 g_dtx[TOK * DI];           // (dt, x_conv)
__device__ float  g_Bv [TOK * NST];
__device__ float  g_Cv [TOK * NST];
__device__ __align__(16) float2 g_ab [GSEQ * NCH * SEG];   // (a_prod, h_end)
__device__ __align__(16) float  g_hs [GSEQ * NCH * SEG];   // h_start
__device__ float  g_ys [GSEQ * LSEQ * DI];

typedef unsigned long long u64;
__device__ __forceinline__ float ex2(float x) {
    float r; asm("ex2.approx.f32 %0, %1;" : "=f"(r) : "f"(x)); return r;
}
__device__ __forceinline__ u64 pack2(float lo, float hi) {
    u64 r; asm("mov.b64 %0, {%1, %2};" : "=l"(r) : "f"(lo), "f"(hi)); return r;
}
__device__ __forceinline__ void unpack2(u64 v, float& lo, float& hi) {
    asm("mov.b64 {%0, %1}, %2;" : "=f"(lo), "=f"(hi) : "l"(v));
}
__device__ __forceinline__ u64 fma2(u64 a, u64 b, u64 c) {
    u64 d; asm("fma.rn.f32x2 %0, %1, %2, %3;" : "=l"(d) : "l"(a), "l"(b), "l"(c)); return d;
}
__device__ __forceinline__ u64 mul2(u64 a, u64 b) {
    u64 d; asm("mul.rn.f32x2 %0, %1, %2;" : "=l"(d) : "l"(a), "l"(b)); return d;
}

__device__ __forceinline__ void seq_base(int d, int b, int ch, int& t0, int& st) {
    if      (d == 0) { t0 = b * LSEQ + ch * WWW;      st = 1;   }
    else if (d == 1) { t0 = b * LSEQ + ch * WWW + 55; st = -1;  }
    else if (d == 2) { t0 = b * LSEQ + ch;            st = WWW; }
    else             { t0 = b * LSEQ + (55 - ch);     st = WWW; }
}

// ---------------- kernel 1: xz = x @ W_in -> xm / z ----------------
__global__ void __launch_bounds__(256) k_inproj(const float* __restrict__ x,
                                                const float* __restrict__ Wi) {
    __shared__ float sx[48 * 64];
    __shared__ float sw[48 * 128];
    const int m0 = blockIdx.x * 64;
    const int n0 = blockIdx.y * 128;
    const int tid = threadIdx.x;
    const int tm = tid >> 4;
    const int tn = tid & 15;
    float acc[4][8] = {};
    for (int k0 = 0; k0 < 96; k0 += 48) {
        __syncthreads();
        for (int idx = tid; idx < 64 * 48; idx += 256) {
            int i = idx / 48, kk = idx - i * 48;
            sx[kk * 64 + i] = x[(m0 + i) * 96 + k0 + kk];
        }
        for (int idx = tid; idx < 48 * 128; idx += 256) {
            int kk = idx >> 7, nn = idx & 127;
            sw[kk * 128 + nn] = Wi[(k0 + kk) * 384 + n0 + nn];
        }
        __syncthreads();
#pragma unroll
        for (int kk = 0; kk < 48; kk++) {
            float4 a  = *(const float4*)&sx[kk * 64  + tm * 4];
            float4 b0 = *(const float4*)&sw[kk * 128 + tn * 8];
            float4 b1 = *(const float4*)&sw[kk * 128 + tn * 8 + 4];
            float av[4] = {a.x, a.y, a.z, a.w};
            float bv[8] = {b0.x, b0.y, b0.z, b0.w, b1.x, b1.y, b1.z, b1.w};
#pragma unroll
            for (int i = 0; i < 4; i++)
#pragma unroll
                for (int j = 0; j < 8; j++)
                    acc[i][j] = fmaf(av[i], bv[j], acc[i][j]);
        }
    }
#pragma unroll
    for (int i = 0; i < 4; i++) {
        int m = m0 + tm * 4 + i;
#pragma unroll
        for (int j = 0; j < 8; j++) {
            int n = n0 + tn * 8 + j;
            if (n < DI) g_xm[m * DI + n] = acc[i][j];
            else        g_z [m * DI + (n - DI)] = acc[i][j];
        }
    }
}

// ---------------- kernel 2: fused conv3x3 + x-proj + dt-proj ----------------
#define SXP 193
#define XN  40
__global__ void __launch_bounds__(256) k_fuse(const float* __restrict__ cw,
                                              const float* __restrict__ cb,
                                              const float* __restrict__ Wx,
                                              const float* __restrict__ Wd,
                                              const float* __restrict__ bd) {
    __shared__ float sxc[32 * SXP];
    __shared__ float sw[48 * XN];
    __shared__ float swd[RK * DI];
    __shared__ float sbd[DI];
    __shared__ float sdtr[32 * 8];
    __shared__ float scw[9 * DI];
    __shared__ float scb[DI];
    const int t0 = blockIdx.x * 32;
    const int tid = threadIdx.x;

    for (int idx = tid; idx < RK * DI; idx += 256) swd[idx] = Wd[idx];
    for (int idx = tid; idx < 9 * DI; idx += 256) scw[idx] = cw[idx];
    if (tid < DI) { sbd[tid] = bd[tid]; scb[tid] = cb[tid]; }
    __syncthreads();

    // conv phase
    for (int idx = tid; idx < 32 * DI; idx += 256) {
        int i = idx / DI, c = idx - i * DI;
        int t = t0 + i;
        int b = t / LSEQ, r = t - b * LSEQ, h = r / WWW, w = r - h * WWW;
        float acc = scb[c];
#pragma unroll
        for (int dh = -1; dh <= 1; dh++)
#pragma unroll
            for (int dw = -1; dw <= 1; dw++) {
                int hh = h + dh, ww = w + dw;
                if ((unsigned)hh < HH && (unsigned)ww < WWW)
                    acc = fmaf(g_xm[(b * LSEQ + hh * WWW + ww) * DI + c],
                               scw[((dh + 1) * 3 + (dw + 1)) * DI + c], acc);
            }
        sxc[i * SXP + c] = acc;
    }

    // x-proj GEMM: M=32, N=38(pad 40), K=192
    const int tm = tid >> 3;
    const int tn = tid & 7;
    float acc[5] = {};
    for (int k0 = 0; k0 < 192; k0 += 48) {
        __syncthreads();
        for (int idx = tid; idx < 48 * XN; idx += 256) {
            int kk = idx / XN, nn = idx - kk * XN;
            sw[idx] = (nn < 38) ? Wx[(k0 + kk) * 38 + nn] : 0.f;
        }
        __syncthreads();
#pragma unroll
        for (int kk = 0; kk < 48; kk++) {
            float a = sxc[tm * SXP + k0 + kk];
            const float* wr = &sw[kk * XN + tn * 5];
#pragma unroll
            for (int j = 0; j < 5; j++) acc[j] = fmaf(a, wr[j], acc[j]);
        }
    }
#pragma unroll
    for (int j = 0; j < 5; j++) {
        int n = tn * 5 + j;
        if (n < RK)            sdtr[tm * 8 + n] = acc[j];
        else if (n < RK + NST) g_Bv[(t0 + tm) * NST + n - RK] = acc[j];
        else if (n < 38)       g_Cv[(t0 + tm) * NST + n - RK - NST] = acc[j];
    }
    __syncthreads();

    // dt-proj + softplus, pack with conv output
#pragma unroll
    for (int p = 0; p < 24; p++) {
        int idx = p * 256 + tid;
        int i = idx / DI, c = idx - i * DI;
        float a = sbd[c];
#pragma unroll
        for (int r = 0; r < RK; r++) a = fmaf(sdtr[i * 8 + r], swd[r * DI + c], a);
        float dt = (a > 20.f) ? a : log1pf(expf(a));
        g_dtx[(t0 + i) * DI + c] = make_float2(dt, sxc[i * SXP + c]);
    }
}

// ---------------- kernel 3: scan pass 1 ----------------
__global__ void __launch_bounds__(192) k_scan1(const float* __restrict__ A_log) {
    const int bx = blockIdx.x;
    const int ch = bx % NCH, g = bx / NCH;
    const int d = g >> 1, b = g & 1;
    __shared__ __align__(16) float s_B[CLEN * NST];
    int t0, st; seq_base(d, b, ch, t0, st);
    const int c = threadIdx.x;
    for (int idx = c; idx < CLEN * NST; idx += 192) {
        int l = idx >> 4, n = idx & 15;
        s_B[idx] = g_Bv[(t0 + l * st) * NST + n];
    }
    float acl[16];
#pragma unroll
    for (int q = 0; q < 4; q++) {
        float4 v = ((const float4*)A_log)[c * 4 + q];
        acl[q*4+0] = -__expf(v.x) * 1.4426950408889634f;
        acl[q*4+1] = -__expf(v.y) * 1.4426950408889634f;
        acl[q*4+2] = -__expf(v.z) * 1.4426950408889634f;
        acl[q*4+3] = -__expf(v.w) * 1.4426950408889634f;
    }
    u64 acl2[8], h2[8];
#pragma unroll
    for (int q = 0; q < 8; q++) { acl2[q] = pack2(acl[2*q], acl[2*q+1]); h2[q] = 0ull; }
    __syncthreads();
    const int stride = st * DI;
    const float2* pdx = g_dtx + t0 * DI + c;
    float2 cur = *pdx;
    float S = 0.f;
#pragma unroll 2
    for (int l = 0; l < CLEN; l++) {
        float dt = cur.x, xv = cur.y;
        if (l < CLEN - 1) { pdx += stride; cur = *pdx; }
        S += dt;
        float dtx = dt * xv;
        u64 dt2  = pack2(dt, dt);
        u64 dtx2 = pack2(dtx, dtx);
        const u64* b2 = (const u64*)(s_B + l * 16);
#pragma unroll
        for (int q = 0; q < 8; q++) {
            u64 arg = mul2(dt2, acl2[q]);
            float alo, ahi; unpack2(arg, alo, ahi);
            u64 a2 = pack2(ex2(alo), ex2(ahi));
            h2[q] = fma2(a2, h2[q], mul2(dtx2, b2[q]));
        }
    }
    float4* pw = (float4*)&g_ab[(bx * DI + c) * NST];
#pragma unroll
    for (int q = 0; q < 8; q++) {
        float h0, h1; unpack2(h2[q], h0, h1);
        pw[q] = make_float4(ex2(acl[2*q] * S), h0, ex2(acl[2*q+1] * S), h1);
    }
}

// ---------------- kernel 4: cross-chunk prefix combine ----------------
__global__ void __launch_bounds__(128) k_combine() {
    const int s = blockIdx.x * 128 + threadIdx.x;   // 24576
    const int g = s / SEG, sc = s - g * SEG;
    const float2* pab = g_ab + g * NCH * SEG + sc;
    float* phs = g_hs + g * NCH * SEG + sc;
    float h = 0.f;
#pragma unroll
    for (int half = 0; half < 2; half++) {
        float2 v[28];
#pragma unroll
        for (int j = 0; j < 28; j++) v[j] = pab[(half * 28 + j) * SEG];
#pragma unroll
        for (int j = 0; j < 28; j++) {
            phs[(half * 28 + j) * SEG] = h;
            h = fmaf(v[j].x, h, v[j].y);
        }
    }
}

// ---------------- kernel 5: scan pass 2 (replay + emit y) ----------------
__global__ void __launch_bounds__(192) k_scan2(const float* __restrict__ A_log,
                                               const float* __restrict__ D_skip) {
    const int bx = blockIdx.x;
    const int ch = bx % NCH, g = bx / NCH;
    const int d = g >> 1, b = g & 1;
    __shared__ __align__(16) float s_B[CLEN * NST];
    __shared__ __align__(16) float s_C[CLEN * NST];
    int t0, st; seq_base(d, b, ch, t0, st);
    const int c = threadIdx.x;
    for (int idx = c; idx < CLEN * NST * 2; idx += 192) {
        int half = idx >= CLEN * NST;
        int r = idx - half * CLEN * NST;
        int l = r >> 4, n = r & 15;
        int t = t0 + l * st;
        if (half) s_C[r] = g_Cv[t * NST + n];
        else      s_B[r] = g_Bv[t * NST + n];
    }
    float acl[16];
#pragma unroll
    for (int q = 0; q < 4; q++) {
        float4 v = ((const float4*)A_log)[c * 4 + q];
        acl[q*4+0] = -__expf(v.x) * 1.4426950408889634f;
        acl[q*4+1] = -__expf(v.y) * 1.4426950408889634f;
        acl[q*4+2] = -__expf(v.z) * 1.4426950408889634f;
        acl[q*4+3] = -__expf(v.w) * 1.4426950408889634f;
    }
    u64 acl2[8], h2[8];
    const int base = (bx * DI + c) * NST;
    const u64* phs = (const u64*)&g_hs[base];
#pragma unroll
    for (int q = 0; q < 8; q++) { acl2[q] = pack2(acl[2*q], acl[2*q+1]); h2[q] = phs[q]; }
    const float dsk = D_skip[c];
    __syncthreads();
    const int stride = st * DI;
    const float2* pdx = g_dtx + t0 * DI + c;
    float2 cur = *pdx;
    float* py = g_ys + (g * LSEQ + ch * CLEN) * DI + c;
#pragma unroll 2
    for (int l = 0; l < CLEN; l++) {
        float dt = cur.x, xv = cur.y;
        if (l < CLEN - 1) { pdx += stride; cur = *pdx; }
        float dtx = dt * xv;
        u64 dt2  = pack2(dt, dt);
        u64 dtx2 = pack2(dtx, dtx);
        const u64* b2 = (const u64*)(s_B + l * 16);
        const u64* c2 = (const u64*)(s_C + l * 16);
        u64 y2 = 0ull;
#pragma unroll
        for (int q = 0; q < 8; q++) {
            u64 arg = mul2(dt2, acl2[q]);
            float alo, ahi; unpack2(arg, alo, ahi);
            u64 a2 = pack2(ex2(alo), ex2(ahi));
            h2[q] = fma2(a2, h2[q], mul2(dtx2, b2[q]));
            y2 = fma2(h2[q], c2[q], y2);
        }
        float ylo, yhi; unpack2(y2, ylo, yhi);
        py[l * DI] = fmaf(dsk, xv, ylo + yhi);
    }
}

// ---------------- kernel 6: sum dirs, silu gate, out-proj ----------------
__global__ void __launch_bounds__(256) k_final(const float* __restrict__ Wo,
                                               float* __restrict__ out) {
    __shared__ float syT[192 * 36];
    __shared__ float sw[48 * 96];
    const int t0 = blockIdx.x * 32;
    const int tid = threadIdx.x;
    for (int idx = tid; idx < 32 * 192; idx += 256) {
        int i = idx / 192, c = idx - i * 192;
        int t = t0 + i; int b = t / LSEQ; int l = t - b * LSEQ;
        float ys = 0.f;
#pragma unroll
        for (int dd = 0; dd < 4; dd++)
            ys += g_ys[((dd * 2 + b) * LSEQ + l) * DI + c];
        float z = g_z[t * DI + c];
        syT[c * 36 + i] = ys * (z / (1.f + __expf(-z)));
    }
    const int tm = tid >> 5;
    const int tn = tid & 31;
    float acc[4][3] = {};
    for (int k0 = 0; k0 < 192; k0 += 48) {
        __syncthreads();
        for (int idx = tid; idx < 48 * 96; idx += 256) {
            int kk = idx / 96, nn = idx - kk * 96;
            sw[idx] = Wo[(k0 + kk) * 96 + nn];
        }
        __syncthreads();
#pragma unroll
        for (int kk = 0; kk < 48; kk++) {
            float4 a = *(const float4*)&syT[(k0 + kk) * 36 + tm * 4];
            float w0 = sw[kk * 96 + tn];
            float w1 = sw[kk * 96 + 32 + tn];
            float w2 = sw[kk * 96 + 64 + tn];
            float av[4] = {a.x, a.y, a.z, a.w};
#pragma unroll
            for (int i = 0; i < 4; i++) {
                acc[i][0] = fmaf(av[i], w0, acc[i][0]);
                acc[i][1] = fmaf(av[i], w1, acc[i][1]);
                acc[i][2] = fmaf(av[i], w2, acc[i][2]);
            }
        }
    }
#pragma unroll
    for (int i = 0; i < 4; i++) {
        int t = t0 + tm * 4 + i;
        out[t * DM + tn]      = acc[i][0];
        out[t * DM + 32 + tn] = acc[i][1];
        out[t * DM + 64 + tn] = acc[i][2];
    }
}

// ---------------- launcher ----------------
extern "C" void kernel_launch(void* const* d_in, const int* in_sizes, int n_in,
                              void* d_out, int out_size) {
    const float* x      = (const float*)d_in[0];
    const float* W_in   = (const float*)d_in[1];
    const float* conv_w = (const float*)d_in[2];
    const float* conv_b = (const float*)d_in[3];
    const float* W_xpr  = (const float*)d_in[4];
    const float* W_dt   = (const float*)d_in[5];
    const float* b_dt   = (const float*)d_in[6];
    const float* A_log  = (const float*)d_in[7];
    const float* D_skip = (const float*)d_in[8];
    const float* W_out  = (const float*)d_in[9];
    float* out = (float*)d_out;

    dim3 g1(TOK / 64, N2 / 128);
    k_inproj<<<g1, 256>>>(x, W_in);
    k_fuse<<<TOK / 32, 256>>>(conv_w, conv_b, W_xpr, W_dt, b_dt);
    k_scan1<<<GSEQ * NCH, 192>>>(A_log);
    k_combine<<<GSEQ * SEG / 128, 128>>>();
    k_scan2<<<GSEQ * NCH, 192>>>(A_log, D_skip);
    k_final<<<TOK / 32, 256>>>(W_out, out);
}

// round 16
// speedup vs baseline: 1.0047x; 1.0045x over previous
#include <cuda_runtime.h>
#include <cuda_bf16.h>
#include <math.h>

// ---------------- problem constants ----------------
#define TOK    6272
#define LSEQ   3136
#define HH     56
#define WWW    56
#define DM     96
#define DI     192
#define N2     384
#define NST    16
#define RK     6
#define GSEQ   8
#define NCH    56
#define CLEN   56
#define SEG    (DI * NST)   // 3072 states per (g,chunk)

// ---------------- scratch ----------------
__device__ float  g_xm [TOK * DI];
__device__ float  g_z  [TOK * DI];
__device__ __align__(16) float2 g_dtx[TOK * DI];           // (dt, x_conv)
__device__ float  g_Bv [TOK * NST];
__device__ float  g_Cv [TOK * NST];
__device__ __align__(16) float2 g_ab [GSEQ * NCH * SEG];   // (a_prod, h_end)
__device__ __align__(16) float  g_hs [GSEQ * NCH * SEG];   // h_start
__device__ float  g_ys [GSEQ * LSEQ * DI];

typedef unsigned long long u64;
__device__ __forceinline__ float ex2(float x) {
    float r; asm("ex2.approx.f32 %0, %1;" : "=f"(r) : "f"(x)); return r;
}
__device__ __forceinline__ u64 pack2(float lo, float hi) {
    u64 r; asm("mov.b64 %0, {%1, %2};" : "=l"(r) : "f"(lo), "f"(hi)); return r;
}
__device__ __forceinline__ void unpack2(u64 v, float& lo, float& hi) {
    asm("mov.b64 {%0, %1}, %2;" : "=f"(lo), "=f"(hi) : "l"(v));
}
__device__ __forceinline__ u64 fma2(u64 a, u64 b, u64 c) {
    u64 d; asm("fma.rn.f32x2 %0, %1, %2, %3;" : "=l"(d) : "l"(a), "l"(b), "l"(c)); return d;
}
__device__ __forceinline__ u64 mul2(u64 a, u64 b) {
    u64 d; asm("mul.rn.f32x2 %0, %1, %2;" : "=l"(d) : "l"(a), "l"(b)); return d;
}

__device__ __forceinline__ void seq_base(int d, int b, int ch, int& t0, int& st) {
    if      (d == 0) { t0 = b * LSEQ + ch * WWW;      st = 1;   }
    else if (d == 1) { t0 = b * LSEQ + ch * WWW + 55; st = -1;  }
    else if (d == 2) { t0 = b * LSEQ + ch;            st = WWW; }
    else             { t0 = b * LSEQ + (55 - ch);     st = WWW; }
}

// ---------------- kernel 1: xz = x @ W_in -> xm / z ----------------
__global__ void __launch_bounds__(256) k_inproj(const float* __restrict__ x,
                                                const float* __restrict__ Wi) {
    __shared__ float sx[48 * 64];
    __shared__ float sw[48 * 128];
    const int m0 = blockIdx.x * 64;
    const int n0 = blockIdx.y * 128;
    const int tid = threadIdx.x;
    const int tm = tid >> 4;
    const int tn = tid & 15;
    float acc[4][8] = {};
    for (int k0 = 0; k0 < 96; k0 += 48) {
        __syncthreads();
        for (int idx = tid; idx < 64 * 48; idx += 256) {
            int i = idx / 48, kk = idx - i * 48;
            sx[kk * 64 + i] = x[(m0 + i) * 96 + k0 + kk];
        }
        for (int idx = tid; idx < 48 * 128; idx += 256) {
            int kk = idx >> 7, nn = idx & 127;
            sw[kk * 128 + nn] = Wi[(k0 + kk) * 384 + n0 + nn];
        }
        __syncthreads();
#pragma unroll
        for (int kk = 0; kk < 48; kk++) {
            float4 a  = *(const float4*)&sx[kk * 64  + tm * 4];
            float4 b0 = *(const float4*)&sw[kk * 128 + tn * 8];
            float4 b1 = *(const float4*)&sw[kk * 128 + tn * 8 + 4];
            float av[4] = {a.x, a.y, a.z, a.w};
            float bv[8] = {b0.x, b0.y, b0.z, b0.w, b1.x, b1.y, b1.z, b1.w};
#pragma unroll
            for (int i = 0; i < 4; i++)
#pragma unroll
                for (int j = 0; j < 8; j++)
                    acc[i][j] = fmaf(av[i], bv[j], acc[i][j]);
        }
    }
#pragma unroll
    for (int i = 0; i < 4; i++) {
        int m = m0 + tm * 4 + i;
#pragma unroll
        for (int j = 0; j < 8; j++) {
            int n = n0 + tn * 8 + j;
            if (n < DI) g_xm[m * DI + n] = acc[i][j];
            else        g_z [m * DI + (n - DI)] = acc[i][j];
        }
    }
}

// ---------------- kernel 2: fused conv3x3 + x-proj + dt-proj ----------------
#define SXP 193
#define XN  40
__global__ void __launch_bounds__(256) k_fuse(const float* __restrict__ cw,
                                              const float* __restrict__ cb,
                                              const float* __restrict__ Wx,
                                              const float* __restrict__ Wd,
                                              const float* __restrict__ bd) {
    __shared__ float sxc[32 * SXP];
    __shared__ float sw[48 * XN];
    __shared__ float swd[RK * DI];
    __shared__ float sbd[DI];
    __shared__ float sdtr[32 * 8];
    __shared__ float scw[9 * DI];
    __shared__ float scb[DI];
    const int t0 = blockIdx.x * 32;
    const int tid = threadIdx.x;

    for (int idx = tid; idx < RK * DI; idx += 256) swd[idx] = Wd[idx];
    for (int idx = tid; idx < 9 * DI; idx += 256) scw[idx] = cw[idx];
    if (tid < DI) { sbd[tid] = bd[tid]; scb[tid] = cb[tid]; }
    __syncthreads();

    // conv phase
    for (int idx = tid; idx < 32 * DI; idx += 256) {
        int i = idx / DI, c = idx - i * DI;
        int t = t0 + i;
        int b = t / LSEQ, r = t - b * LSEQ, h = r / WWW, w = r - h * WWW;
        float acc = scb[c];
#pragma unroll
        for (int dh = -1; dh <= 1; dh++)
#pragma unroll
            for (int dw = -1; dw <= 1; dw++) {
                int hh = h + dh, ww = w + dw;
                if ((unsigned)hh < HH && (unsigned)ww < WWW)
                    acc = fmaf(g_xm[(b * LSEQ + hh * WWW + ww) * DI + c],
                               scw[((dh + 1) * 3 + (dw + 1)) * DI + c], acc);
            }
        sxc[i * SXP + c] = acc;
    }

    // x-proj GEMM: M=32, N=38(pad 40), K=192
    const int tm = tid >> 3;
    const int tn = tid & 7;
    float acc[5] = {};
    for (int k0 = 0; k0 < 192; k0 += 48) {
        __syncthreads();
        for (int idx = tid; idx < 48 * XN; idx += 256) {
            int kk = idx / XN, nn = idx - kk * XN;
            sw[idx] = (nn < 38) ? Wx[(k0 + kk) * 38 + nn] : 0.f;
        }
        __syncthreads();
#pragma unroll
        for (int kk = 0; kk < 48; kk++) {
            float a = sxc[tm * SXP + k0 + kk];
            const float* wr = &sw[kk * XN + tn * 5];
#pragma unroll
            for (int j = 0; j < 5; j++) acc[j] = fmaf(a, wr[j], acc[j]);
        }
    }
#pragma unroll
    for (int j = 0; j < 5; j++) {
        int n = tn * 5 + j;
        if (n < RK)            sdtr[tm * 8 + n] = acc[j];
        else if (n < RK + NST) g_Bv[(t0 + tm) * NST + n - RK] = acc[j];
        else if (n < 38)       g_Cv[(t0 + tm) * NST + n - RK - NST] = acc[j];
    }
    __syncthreads();

    // dt-proj + softplus, pack with conv output
#pragma unroll
    for (int p = 0; p < 24; p++) {
        int idx = p * 256 + tid;
        int i = idx / DI, c = idx - i * DI;
        float a = sbd[c];
#pragma unroll
        for (int r = 0; r < RK; r++) a = fmaf(sdtr[i * 8 + r], swd[r * DI + c], a);
        float dt = (a > 20.f) ? a : log1pf(expf(a));
        g_dtx[(t0 + i) * DI + c] = make_float2(dt, sxc[i * SXP + c]);
    }
}

// ---------------- kernel 3: scan pass 1 ----------------
__global__ void __launch_bounds__(192) k_scan1(const float* __restrict__ A_log) {
    const int bx = blockIdx.x;
    const int ch = bx % NCH, g = bx / NCH;
    const int d = g >> 1, b = g & 1;
    __shared__ __align__(16) float s_B[CLEN * NST];
    int t0, st; seq_base(d, b, ch, t0, st);
    const int c = threadIdx.x;
    for (int idx = c; idx < CLEN * NST; idx += 192) {
        int l = idx >> 4, n = idx & 15;
        s_B[idx] = g_Bv[(t0 + l * st) * NST + n];
    }
    float acl[16];
#pragma unroll
    for (int q = 0; q < 4; q++) {
        float4 v = ((const float4*)A_log)[c * 4 + q];
        acl[q*4+0] = -__expf(v.x) * 1.4426950408889634f;
        acl[q*4+1] = -__expf(v.y) * 1.4426950408889634f;
        acl[q*4+2] = -__expf(v.z) * 1.4426950408889634f;
        acl[q*4+3] = -__expf(v.w) * 1.4426950408889634f;
    }
    u64 acl2[8], h2[8];
#pragma unroll
    for (int q = 0; q < 8; q++) { acl2[q] = pack2(acl[2*q], acl[2*q+1]); h2[q] = 0ull; }
    __syncthreads();
    const int stride = st * DI;
    const float2* pdx = g_dtx + t0 * DI + c;
    float2 cur = *pdx;
    float S = 0.f;
#pragma unroll 2
    for (int l = 0; l < CLEN; l++) {
        float dt = cur.x, xv = cur.y;
        if (l < CLEN - 1) { pdx += stride; cur = *pdx; }
        S += dt;
        float dtx = dt * xv;
        u64 dt2  = pack2(dt, dt);
        u64 dtx2 = pack2(dtx, dtx);
        const u64* b2 = (const u64*)(s_B + l * 16);
#pragma unroll
        for (int q = 0; q < 8; q++) {
            u64 arg = mul2(dt2, acl2[q]);
            float alo, ahi; unpack2(arg, alo, ahi);
            u64 a2 = pack2(ex2(alo), ex2(ahi));
            h2[q] = fma2(a2, h2[q], mul2(dtx2, b2[q]));
        }
    }
    float4* pw = (float4*)&g_ab[(bx * DI + c) * NST];
#pragma unroll
    for (int q = 0; q < 8; q++) {
        float h0, h1; unpack2(h2[q], h0, h1);
        pw[q] = make_float4(ex2(acl[2*q] * S), h0, ex2(acl[2*q+1] * S), h1);
    }
}

// ---------------- kernel 4: cross-chunk prefix combine ----------------
__global__ void __launch_bounds__(128) k_combine() {
    const int s = blockIdx.x * 128 + threadIdx.x;   // 24576
    const int g = s / SEG, sc = s - g * SEG;
    const float2* pab = g_ab + g * NCH * SEG + sc;
    float* phs = g_hs + g * NCH * SEG + sc;
    float h = 0.f;
#pragma unroll
    for (int half = 0; half < 2; half++) {
        float2 v[28];
#pragma unroll
        for (int j = 0; j < 28; j++) v[j] = pab[(half * 28 + j) * SEG];
#pragma unroll
        for (int j = 0; j < 28; j++) {
            phs[(half * 28 + j) * SEG] = h;
            h = fmaf(v[j].x, h, v[j].y);
        }
    }
}

// ---------------- kernel 5: scan pass 2 (replay + emit y) ----------------
__global__ void __launch_bounds__(192) k_scan2(const float* __restrict__ A_log,
                                               const float* __restrict__ D_skip) {
    const int bx = blockIdx.x;
    const int ch = bx % NCH, g = bx / NCH;
    const int d = g >> 1, b = g & 1;
    __shared__ __align__(16) float s_B[CLEN * NST];
    __shared__ __align__(16) float s_C[CLEN * NST];
    int t0, st; seq_base(d, b, ch, t0, st);
    const int c = threadIdx.x;
    for (int idx = c; idx < CLEN * NST * 2; idx += 192) {
        int half = idx >= CLEN * NST;
        int r = idx - half * CLEN * NST;
        int l = r >> 4, n = r & 15;
        int t = t0 + l * st;
        if (half) s_C[r] = g_Cv[t * NST + n];
        else      s_B[r] = g_Bv[t * NST + n];
    }
    float acl[16];
#pragma unroll
    for (int q = 0; q < 4; q++) {
        float4 v = ((const float4*)A_log)[c * 4 + q];
        acl[q*4+0] = -__expf(v.x) * 1.4426950408889634f;
        acl[q*4+1] = -__expf(v.y) * 1.4426950408889634f;
        acl[q*4+2] = -__expf(v.z) * 1.4426950408889634f;
        acl[q*4+3] = -__expf(v.w) * 1.4426950408889634f;
    }
    u64 acl2[8], h2[8];
    const int base = (bx * DI + c) * NST;
    const u64* phs = (const u64*)&g_hs[base];
#pragma unroll
    for (int q = 0; q < 8; q++) { acl2[q] = pack2(acl[2*q], acl[2*q+1]); h2[q] = phs[q]; }
    const float dsk = D_skip[c];
    __syncthreads();
    const int stride = st * DI;
    const float2* pdx = g_dtx + t0 * DI + c;
    float2 cur = *pdx;
    float* py = g_ys + (g * LSEQ + ch * CLEN) * DI + c;
#pragma unroll 2
    for (int l = 0; l < CLEN; l++) {
        float dt = cur.x, xv = cur.y;
        if (l < CLEN - 1) { pdx += stride; cur = *pdx; }
        float dtx = dt * xv;
        u64 dt2  = pack2(dt, dt);
        u64 dtx2 = pack2(dtx, dtx);
        const u64* b2 = (const u64*)(s_B + l * 16);
        const u64* c2 = (const u64*)(s_C + l * 16);
        u64 y2 = 0ull;
#pragma unroll
        for (int q = 0; q < 8; q++) {
            u64 arg = mul2(dt2, acl2[q]);
            float alo, ahi; unpack2(arg, alo, ahi);
            u64 a2 = pack2(ex2(alo), ex2(ahi));
            h2[q] = fma2(a2, h2[q], mul2(dtx2, b2[q]));
            y2 = fma2(h2[q], c2[q], y2);
        }
        float ylo, yhi; unpack2(y2, ylo, yhi);
        py[l * DI] = fmaf(dsk, xv, ylo + yhi);
    }
}

// ---------------- kernel 6: sum dirs, silu gate, out-proj ----------------
__global__ void __launch_bounds__(256) k_final(const float* __restrict__ Wo,
                                               float* __restrict__ out) {
    __shared__ float syT[192 * 36];
    __shared__ float sw[48 * 96];
    const int t0 = blockIdx.x * 32;
    const int tid = threadIdx.x;
    for (int idx = tid; idx < 32 * 192; idx += 256) {
        int i = idx / 192, c = idx - i * 192;
        int t = t0 + i; int b = t / LSEQ; int l = t - b * LSEQ;
        float ys = 0.f;
#pragma unroll
        for (int dd = 0; dd < 4; dd++)
            ys += g_ys[((dd * 2 + b) * LSEQ + l) * DI + c];
        float z = g_z[t * DI + c];
        syT[c * 36 + i] = ys * (z / (1.f + __expf(-z)));
    }
    const int tm = tid >> 5;
    const int tn = tid & 31;
    float acc[4][3] = {};
    for (int k0 = 0; k0 < 192; k0 += 48) {
        __syncthreads();
        for (int idx = tid; idx < 48 * 96; idx += 256) {
            int kk = idx / 96, nn = idx - kk * 96;
            sw[idx] = Wo[(k0 + kk) * 96 + nn];
        }
        __syncthreads();
#pragma unroll
        for (int kk = 0; kk < 48; kk++) {
            float4 a = *(const float4*)&syT[(k0 + kk) * 36 + tm * 4];
            float w0 = sw[kk * 96 + tn];
            float w1 = sw[kk * 96 + 32 + tn];
            float w2 = sw[kk * 96 + 64 + tn];
            float av[4] = {a.x, a.y, a.z, a.w};
#pragma unroll
            for (int i = 0; i < 4; i++) {
                acc[i][0] = fmaf(av[i], w0, acc[i][0]);
                acc[i][1] = fmaf(av[i], w1, acc[i][1]);
                acc[i][2] = fmaf(av[i], w2, acc[i][2]);
            }
        }
    }
#pragma unroll
    for (int i = 0; i < 4; i++) {
        int t = t0 + tm * 4 + i;
        out[t * DM + tn]      = acc[i][0];
        out[t * DM + 32 + tn] = acc[i][1];
        out[t * DM + 64 + tn] = acc[i][2];
    }
}

// ---------------- launcher ----------------
extern "C" void kernel_launch(void* const* d_in, const int* in_sizes, int n_in,
                              void* d_out, int out_size) {
    const float* x      = (const float*)d_in[0];
    const float* W_in   = (const float*)d_in[1];
    const float* conv_w = (const float*)d_in[2];
    const float* conv_b = (const float*)d_in[3];
    const float* W_xpr  = (const float*)d_in[4];
    const float* W_dt   = (const float*)d_in[5];
    const float* b_dt   = (const float*)d_in[6];
    const float* A_log  = (const float*)d_in[7];
    const float* D_skip = (const float*)d_in[8];
    const float* W_out  = (const float*)d_in[9];
    float* out = (float*)d_out;

    dim3 g1(TOK / 64, N2 / 128);
    k_inproj<<<g1, 256>>>(x, W_in);
    k_fuse<<<TOK / 32, 256>>>(conv_w, conv_b, W_xpr, W_dt, b_dt);
    k_scan1<<<GSEQ * NCH, 192>>>(A_log);
    k_combine<<<GSEQ * SEG / 128, 128>>>();
    k_scan2<<<GSEQ * NCH, 192>>>(A_log, D_skip);
    k_final<<<TOK / 32, 256>>>(W_out, out);
}